// round 10
// baseline (speedup 1.0000x reference)
#include <cuda_runtime.h>
#include <cuda_fp16.h>

#define N_ANG 720
#define N_DET 1024
#define HIMG 512
#define WIMG 512
#define KSZ 11
#define NB 8

#define WBINS 36      // staged window bins per angle (max needed k = 33)
#define DEPTH 4       // cp.async ring depth

// Filtered sinogram, fp16, layout [angle][det_bin][batch0..7] -> 16B per bin.
__device__ __align__(16) __half g_h[N_ANG * N_DET * NB];

// ---------------------------------------------------------------------------
// Stage 1: causal K=11 cross-correlation (unchanged from r6).
// ---------------------------------------------------------------------------
__global__ void __launch_bounds__(256) conv_kernel(const float* __restrict__ x,
                                                   const float* __restrict__ w) {
    int tx = threadIdx.x;
    int a  = blockIdx.x;

    float wk[KSZ];
#pragma unroll
    for (int k = 0; k < KSZ; ++k) wk[k] = __ldg(w + k);

    uint4 out[4];
#pragma unroll
    for (int bp = 0; bp < 4; ++bp) {
        float acc[2][4];
#pragma unroll
        for (int s = 0; s < 2; ++s) {
            int b = bp * 2 + s;
            const float4* xb = reinterpret_cast<const float4*>(
                x + (size_t)b * (N_ANG * N_DET) + (size_t)a * N_DET);
            float win[16];
#pragma unroll
            for (int q = 0; q < 4; ++q) {
                int qi = tx - 3 + q;
                float4 v;
                if (qi >= 0) v = __ldg(xb + qi);
                else         v = make_float4(0.f, 0.f, 0.f, 0.f);
                win[q * 4 + 0] = v.x; win[q * 4 + 1] = v.y;
                win[q * 4 + 2] = v.z; win[q * 4 + 3] = v.w;
            }
#pragma unroll
            for (int di = 0; di < 4; ++di) {
                float acc_ = 0.f;
#pragma unroll
                for (int k = 0; k < KSZ; ++k)
                    acc_ = fmaf(wk[k], win[di + k + 2], acc_);
                acc[s][di] = acc_;
            }
        }
#pragma unroll
        for (int di = 0; di < 4; ++di) {
            __half2 h = __floats2half2_rn(acc[0][di], acc[1][di]);
            reinterpret_cast<unsigned int*>(&out[di])[bp] =
                *reinterpret_cast<unsigned int*>(&h);
        }
    }

    uint4* gp = reinterpret_cast<uint4*>(g_h) + ((size_t)a << 10) + (tx << 2);
#pragma unroll
    for (int di = 0; di < 4; ++di) gp[di] = out[di];
}

// ---------------------------------------------------------------------------
// Stage 2: backprojection with SMEM-staged detector windows.
// Per angle the CTA tile (8j x 32i) touches a contiguous window of <=34 bins
// (span 31|cos|+7sin+2). cp.async.cg stages bins [base, base+36) into a
// depth-4 ring, 3 angles ahead; pixels gather with conflict-free LDS.128
// (4 wavefronts exact, no cache-line-split overhead). Math identical to r6.
// ---------------------------------------------------------------------------
__device__ __forceinline__ unsigned smem_u32(const void* p) {
    return (unsigned)__cvta_generic_to_shared(p);
}

__global__ void __launch_bounds__(256, 4) bp_kernel(float* __restrict__ out) {
    __shared__ float2 trig[N_ANG];                    // (cos/DS, sin/DS)
    __shared__ __align__(16) uint4 win[DEPTH][WBINS]; // staged bin windows

    const float DTH = 3.14159265358979323846f / (float)N_ANG;
    const float DX  = 2.0f / (float)HIMG;
    const float INV_DS = (float)N_DET / 4.0f;   // 256

    int tx = threadIdx.x;
    for (int a = tx; a < N_ANG; a += blockDim.x) {
        float th = ((float)a + 0.5f) * DTH;
        float s, c;
        sincosf(th, &s, &c);
        trig[a] = make_float2(c * INV_DS, s * INV_DS);
    }
    __syncthreads();

    int j = (blockIdx.x << 3) + (tx & 7);
    int i = (blockIdx.y << 5) + (tx >> 3);
    float xc = fmaf((float)i + 0.5f, DX, -1.0f);
    float yc = fmaf((float)j + 0.5f, DX, -1.0f);

    // CTA-tile corner coords (for window base)
    int iBlk = blockIdx.y << 5;
    int jBlk = blockIdx.x << 3;
    float xcLo = fmaf((float)iBlk + 0.5f,        DX, -1.0f);
    float xcHi = fmaf((float)(iBlk + 31) + 0.5f, DX, -1.0f);
    float ycLo = fmaf((float)jBlk + 0.5f,        DX, -1.0f);

    float fa[NB];
#pragma unroll
    for (int b = 0; b < NB; ++b) fa[b] = 0.f;

    const char* gbase = reinterpret_cast<const char*>(g_h);
    const __half2 one2  = __float2half2_rn(1.0f);
    const __half2 zero2 = __float2half2_rn(0.0f);

    // ---- staging helper (lambda-free macro) -------------------------------
#define STAGE(AA) do {                                                        \
    int a_ = (AA);                                                            \
    if (a_ < N_ANG && tx < WBINS) {                                           \
        float2 cs_ = trig[a_];                                                \
        float xsel_ = (cs_.x >= 0.f) ? xcLo : xcHi;                           \
        float um_ = fmaf(xsel_, cs_.x, fmaf(ycLo, cs_.y, 511.5f));            \
        float tb_ = __fadd_rd(um_, 8388608.0f);                               \
        int base_ = (int)(__float_as_uint(tb_) & 0x007FFFFFu);                \
        const char* gp_ = gbase + ((size_t)a_ << 14) + ((size_t)(base_ + tx) << 4); \
        unsigned daddr_ = smem_u32(&win[a_ & (DEPTH - 1)][tx]);               \
        asm volatile("cp.async.cg.shared.global [%0], [%1], 16;"              \
                     :: "r"(daddr_), "l"(gp_) : "memory");                    \
    }                                                                         \
    asm volatile("cp.async.commit_group;" ::: "memory");                      \
} while (0)

    // prologue: stage angles 0,1,2 (3 groups in flight)
    STAGE(0);
    STAGE(1);
    STAGE(2);

#pragma unroll 1
    for (int a0 = 0; a0 < N_ANG; a0 += 8) {
        __half2 accF0 = zero2, accF1 = zero2, accF2 = zero2, accF3 = zero2;
        __half2 accL0 = zero2, accL1 = zero2, accL2 = zero2, accL3 = zero2;

#pragma unroll
        for (int k = 0; k < 8; ++k) {
            int a = a0 + k;

            // angle a's window complete (all but 2 most-recent groups done)
            asm volatile("cp.async.wait_group 2;" ::: "memory");
            __syncthreads();                 // visible to all; prev buf free
            STAGE(a + 3);                    // overwrite win[(a-1)%4]

            float2 cs = trig[a];
            float u  = fmaf(xc, cs.x, fmaf(yc, cs.y, 511.5f));
            float t  = __fadd_rd(u, 8388608.0f);
            float fi = t - 8388608.0f;       // exact floor(u)
            float f  = u - fi;               // exact, [0,1)

            // window base for this angle (same formula as stager)
            float xsel = (cs.x >= 0.f) ? xcLo : xcHi;
            float um = fmaf(xsel, cs.x, fmaf(ycLo, cs.y, 511.5f));
            float tb = __fadd_rd(um, 8388608.0f);
            float basef = tb - 8388608.0f;
            int kk = (int)(fi - basef);      // 0..33

            const uint4* wp = &win[a & (DEPTH - 1)][0];
            uint4 lo = wp[kk];
            uint4 hi = wp[kk + 1];

            __half2 f2   = __float2half2_rn(f);
            __half2 omf2 = __hsub2(one2, f2);

            accF0 = __hfma2(f2,   *reinterpret_cast<__half2*>(&hi.x), accF0);
            accL0 = __hfma2(omf2, *reinterpret_cast<__half2*>(&lo.x), accL0);
            accF1 = __hfma2(f2,   *reinterpret_cast<__half2*>(&hi.y), accF1);
            accL1 = __hfma2(omf2, *reinterpret_cast<__half2*>(&lo.y), accL1);
            accF2 = __hfma2(f2,   *reinterpret_cast<__half2*>(&hi.z), accF2);
            accL2 = __hfma2(omf2, *reinterpret_cast<__half2*>(&lo.z), accL2);
            accF3 = __hfma2(f2,   *reinterpret_cast<__half2*>(&hi.w), accF3);
            accL3 = __hfma2(omf2, *reinterpret_cast<__half2*>(&lo.w), accL3);
        }

        float2 v;
        __half2 s0 = __hadd2(accF0, accL0);
        __half2 s1 = __hadd2(accF1, accL1);
        __half2 s2 = __hadd2(accF2, accL2);
        __half2 s3 = __hadd2(accF3, accL3);
        v = __half22float2(s0); fa[0] += v.x; fa[1] += v.y;
        v = __half22float2(s1); fa[2] += v.x; fa[3] += v.y;
        v = __half22float2(s2); fa[4] += v.x; fa[5] += v.y;
        v = __half22float2(s3); fa[6] += v.x; fa[7] += v.y;
    }

    int p = i * WIMG + j;
#pragma unroll
    for (int b = 0; b < NB; ++b)
        out[b * (HIMG * WIMG) + p] = fa[b] * DTH;
#undef STAGE
}

// ---------------------------------------------------------------------------
extern "C" void kernel_launch(void* const* d_in, const int* in_sizes, int n_in,
                              void* d_out, int out_size) {
    const float* x = (const float*)d_in[0];   // [8,1,720,1024]
    const float* w = (const float*)d_in[1];   // [1,1,1,11]
    float* out = (float*)d_out;               // [8,1,512,512]

    conv_kernel<<<N_ANG, 256>>>(x, w);
    dim3 grid(WIMG / 8, HIMG / 32);           // (64, 16)
    bp_kernel<<<grid, 256>>>(out);
}

// round 11
// speedup vs baseline: 1.3299x; 1.3299x over previous
#include <cuda_runtime.h>
#include <cuda_fp16.h>

#define N_ANG 720
#define N_HALF 360
#define N_DET 1024
#define HIMG 512
#define WIMG 512
#define KSZ 11
#define NB 8

// Filtered sinogram, fp16, layout [angle][det_bin][batch0..7] -> 16B per bin.
__device__ __align__(16) __half g_h[N_ANG * N_DET * NB];

// ---------------------------------------------------------------------------
// Stage 1: causal K=11 cross-correlation. One thread = (angle a, 4 consecutive
// detector bins), all 8 batches.
// ---------------------------------------------------------------------------
__global__ void __launch_bounds__(256) conv_kernel(const float* __restrict__ x,
                                                   const float* __restrict__ w) {
    int tx = threadIdx.x;        // detector quad index 0..255
    int a  = blockIdx.x;         // angle

    float wk[KSZ];
#pragma unroll
    for (int k = 0; k < KSZ; ++k) wk[k] = __ldg(w + k);

    uint4 out[4];
#pragma unroll
    for (int bp = 0; bp < 4; ++bp) {          // batch pairs
        float acc[2][4];
#pragma unroll
        for (int s = 0; s < 2; ++s) {
            int b = bp * 2 + s;
            const float4* xb = reinterpret_cast<const float4*>(
                x + (size_t)b * (N_ANG * N_DET) + (size_t)a * N_DET);
            float win[16];
#pragma unroll
            for (int q = 0; q < 4; ++q) {
                int qi = tx - 3 + q;
                float4 v;
                if (qi >= 0) v = __ldg(xb + qi);
                else         v = make_float4(0.f, 0.f, 0.f, 0.f);
                win[q * 4 + 0] = v.x; win[q * 4 + 1] = v.y;
                win[q * 4 + 2] = v.z; win[q * 4 + 3] = v.w;
            }
#pragma unroll
            for (int di = 0; di < 4; ++di) {
                float acc_ = 0.f;
#pragma unroll
                for (int k = 0; k < KSZ; ++k)
                    acc_ = fmaf(wk[k], win[di + k + 2], acc_);
                acc[s][di] = acc_;
            }
        }
#pragma unroll
        for (int di = 0; di < 4; ++di) {
            __half2 h = __floats2half2_rn(acc[0][di], acc[1][di]);
            reinterpret_cast<unsigned int*>(&out[di])[bp] =
                *reinterpret_cast<unsigned int*>(&h);
        }
    }

    uint4* gp = reinterpret_cast<uint4*>(g_h) + ((size_t)a << 10) + (tx << 2);
#pragma unroll
    for (int di = 0; di < 4; ++di) gp[di] = out[di];
}

// ---------------------------------------------------------------------------
// Stage 2: backprojection, r7 structure + angle interleaving.
// Each inner step processes the COMPLEMENTARY pair (a, a+360):
//   theta+pi/2  ->  cos' = -sin, sin' = cos
//   u_lo = 511.5 + xc*c + yc*s      (angle a)
//   u_hi = 511.5 - xc*s + yc*c      (angle a+360, trig derived -> no 2nd LDS)
// Their warp detector-spans (7|s|+3|c| and 7|c|+3|s|) sum ~constant, so the
// per-batch L1 wavefront demand is flat instead of swinging 8..16 — L1 stays
// saturated instead of alternating with issue-bound stretches.
// Split half2 accumulators over 8 angles (4 pairs), flushed to fp32.
// ---------------------------------------------------------------------------
__global__ void __launch_bounds__(256, 4) bp_kernel(float* __restrict__ out) {
    __shared__ float2 trig[N_HALF];       // (cos*256, sin*256) for a<360

    const float DTH = 3.14159265358979323846f / (float)N_ANG;
    const float DX  = 2.0f / (float)HIMG;
    const float INV_DS = (float)N_DET / 4.0f;   // 256

    int tx = threadIdx.x;
    for (int a = tx; a < N_HALF; a += blockDim.x) {
        float th = ((float)a + 0.5f) * DTH;
        float s, c;
        sincosf(th, &s, &c);
        trig[a] = make_float2(c * INV_DS, s * INV_DS);
    }
    __syncthreads();

    int j = (blockIdx.x << 3) + (tx & 7);
    int i = (blockIdx.y << 5) + (tx >> 3);
    float xc = fmaf((float)i + 0.5f, DX, -1.0f);
    float yc = fmaf((float)j + 0.5f, DX, -1.0f);

    float fa[NB];
#pragma unroll
    for (int b = 0; b < NB; ++b) fa[b] = 0.f;

    const char* gbase = reinterpret_cast<const char*>(g_h);
    const __half2 one2  = __float2half2_rn(1.0f);
    const __half2 zero2 = __float2half2_rn(0.0f);

#pragma unroll 1
    for (int a0 = 0; a0 < N_HALF; a0 += 4) {
        __half2 accF0 = zero2, accF1 = zero2, accF2 = zero2, accF3 = zero2;
        __half2 accL0 = zero2, accL1 = zero2, accL2 = zero2, accL3 = zero2;

#pragma unroll
        for (int k = 0; k < 4; ++k) {
            int a = a0 + k;
            float2 cs = trig[a];

            // ---- phase A: both angles' address math ----
            float uL = fmaf(xc, cs.x, fmaf(yc, cs.y, 511.5f));   // angle a
            float uH = fmaf(yc, cs.x, fmaf(-xc, cs.y, 511.5f));  // angle a+360

            float tL  = __fadd_rd(uL, 8388608.0f);
            float fiL = tL - 8388608.0f;
            float fL  = uL - fiL;
            unsigned offL = (__float_as_uint(tL) << 9) >> 5;     // i0*16

            float tH  = __fadd_rd(uH, 8388608.0f);
            float fiH = tH - 8388608.0f;
            float fH  = uH - fiH;
            unsigned offH = (__float_as_uint(tH) << 9) >> 5;

            // ---- phase B: 4 LDG.128 (2 per angle) ----
            const uint4* pL = reinterpret_cast<const uint4*>(
                gbase + ((size_t)a << 14) + offL);
            const uint4* pH = reinterpret_cast<const uint4*>(
                gbase + ((size_t)(a + N_HALF) << 14) + offH);
            uint4 L0 = __ldg(pL);
            uint4 L1 = __ldg(pL + 1);
            uint4 H0 = __ldg(pH);
            uint4 H1 = __ldg(pH + 1);

            // ---- phase C: consume both angles ----
            __half2 f2L   = __float2half2_rn(fL);
            __half2 omf2L = __hsub2(one2, f2L);
            accF0 = __hfma2(f2L,   *reinterpret_cast<__half2*>(&L1.x), accF0);
            accL0 = __hfma2(omf2L, *reinterpret_cast<__half2*>(&L0.x), accL0);
            accF1 = __hfma2(f2L,   *reinterpret_cast<__half2*>(&L1.y), accF1);
            accL1 = __hfma2(omf2L, *reinterpret_cast<__half2*>(&L0.y), accL1);
            accF2 = __hfma2(f2L,   *reinterpret_cast<__half2*>(&L1.z), accF2);
            accL2 = __hfma2(omf2L, *reinterpret_cast<__half2*>(&L0.z), accL2);
            accF3 = __hfma2(f2L,   *reinterpret_cast<__half2*>(&L1.w), accF3);
            accL3 = __hfma2(omf2L, *reinterpret_cast<__half2*>(&L0.w), accL3);

            __half2 f2H   = __float2half2_rn(fH);
            __half2 omf2H = __hsub2(one2, f2H);
            accF0 = __hfma2(f2H,   *reinterpret_cast<__half2*>(&H1.x), accF0);
            accL0 = __hfma2(omf2H, *reinterpret_cast<__half2*>(&H0.x), accL0);
            accF1 = __hfma2(f2H,   *reinterpret_cast<__half2*>(&H1.y), accF1);
            accL1 = __hfma2(omf2H, *reinterpret_cast<__half2*>(&H0.y), accL1);
            accF2 = __hfma2(f2H,   *reinterpret_cast<__half2*>(&H1.z), accF2);
            accL2 = __hfma2(omf2H, *reinterpret_cast<__half2*>(&H0.z), accL2);
            accF3 = __hfma2(f2H,   *reinterpret_cast<__half2*>(&H1.w), accF3);
            accL3 = __hfma2(omf2H, *reinterpret_cast<__half2*>(&H0.w), accL3);
        }

        float2 v;
        __half2 s0 = __hadd2(accF0, accL0);
        __half2 s1 = __hadd2(accF1, accL1);
        __half2 s2 = __hadd2(accF2, accL2);
        __half2 s3 = __hadd2(accF3, accL3);
        v = __half22float2(s0); fa[0] += v.x; fa[1] += v.y;
        v = __half22float2(s1); fa[2] += v.x; fa[3] += v.y;
        v = __half22float2(s2); fa[4] += v.x; fa[5] += v.y;
        v = __half22float2(s3); fa[6] += v.x; fa[7] += v.y;
    }

    int p = i * WIMG + j;
#pragma unroll
    for (int b = 0; b < NB; ++b)
        out[b * (HIMG * WIMG) + p] = fa[b] * DTH;
}

// ---------------------------------------------------------------------------
extern "C" void kernel_launch(void* const* d_in, const int* in_sizes, int n_in,
                              void* d_out, int out_size) {
    const float* x = (const float*)d_in[0];   // [8,1,720,1024]
    const float* w = (const float*)d_in[1];   // [1,1,1,11]
    float* out = (float*)d_out;               // [8,1,512,512]

    conv_kernel<<<N_ANG, 256>>>(x, w);
    dim3 grid(WIMG / 8, HIMG / 32);           // (64, 16)
    bp_kernel<<<grid, 256>>>(out);
}

// round 12
// speedup vs baseline: 1.3391x; 1.0069x over previous
#include <cuda_runtime.h>
#include <cuda_fp16.h>

#define N_ANG 720
#define N_HALF 360
#define N_DET 1024
#define HIMG 512
#define WIMG 512
#define KSZ 11
#define NB 8

// Filtered sinogram, fp16, layout [angle][det_bin][batch0..7] -> 16B per bin.
__device__ __align__(16) __half g_h[N_ANG * N_DET * NB];

// ---------------------------------------------------------------------------
// Stage 1: causal K=11 cross-correlation (unchanged).
// ---------------------------------------------------------------------------
__global__ void __launch_bounds__(256) conv_kernel(const float* __restrict__ x,
                                                   const float* __restrict__ w) {
    int tx = threadIdx.x;
    int a  = blockIdx.x;

    float wk[KSZ];
#pragma unroll
    for (int k = 0; k < KSZ; ++k) wk[k] = __ldg(w + k);

    uint4 out[4];
#pragma unroll
    for (int bp = 0; bp < 4; ++bp) {
        float acc[2][4];
#pragma unroll
        for (int s = 0; s < 2; ++s) {
            int b = bp * 2 + s;
            const float4* xb = reinterpret_cast<const float4*>(
                x + (size_t)b * (N_ANG * N_DET) + (size_t)a * N_DET);
            float win[16];
#pragma unroll
            for (int q = 0; q < 4; ++q) {
                int qi = tx - 3 + q;
                float4 v;
                if (qi >= 0) v = __ldg(xb + qi);
                else         v = make_float4(0.f, 0.f, 0.f, 0.f);
                win[q * 4 + 0] = v.x; win[q * 4 + 1] = v.y;
                win[q * 4 + 2] = v.z; win[q * 4 + 3] = v.w;
            }
#pragma unroll
            for (int di = 0; di < 4; ++di) {
                float acc_ = 0.f;
#pragma unroll
                for (int k = 0; k < KSZ; ++k)
                    acc_ = fmaf(wk[k], win[di + k + 2], acc_);
                acc[s][di] = acc_;
            }
        }
#pragma unroll
        for (int di = 0; di < 4; ++di) {
            __half2 h = __floats2half2_rn(acc[0][di], acc[1][di]);
            reinterpret_cast<unsigned int*>(&out[di])[bp] =
                *reinterpret_cast<unsigned int*>(&h);
        }
    }

    uint4* gp = reinterpret_cast<uint4*>(g_h) + ((size_t)a << 10) + (tx << 2);
#pragma unroll
    for (int di = 0; di < 4; ++di) gp[di] = out[di];
}

// ---------------------------------------------------------------------------
// Stage 2: backprojection. One thread = pixel pair (i, i+1) at one j, all 8
// batches, complementary angle pairs (a, a+360).
//  L angle a:        u = xc*cI + yc*sI + 511.5,  du/di = +cos -> window base..base+2
//  H angle a+360:    u = -xc*sI + yc*cI + 511.5, du/di = -sin -> window base-1..base+1
// 3 LDG.128 per angle serve BOTH pixels (6 phases / pixel-angle vs 8).
// Warp phase span unchanged from r11 (8 j-lanes at one i-pair).
// pixel0: 2-tap (1-f, f). pixel1: branch-free 3-point weights on g.
// Split half2 accumulators, flushed to fp32 every 4 angle-pairs (8 angles).
// ---------------------------------------------------------------------------
__global__ void __launch_bounds__(256, 3) bp_kernel(float* __restrict__ out) {
    __shared__ float4 trig[N_HALF];   // (cos*256, sin*256, cos, sin)

    const float DTH = 3.14159265358979323846f / (float)N_ANG;
    const float DX  = 2.0f / (float)HIMG;
    const float INV_DS = (float)N_DET / 4.0f;   // 256

    int tx = threadIdx.x;
    for (int a = tx; a < N_HALF; a += blockDim.x) {
        float th = ((float)a + 0.5f) * DTH;
        float s, c;
        sincosf(th, &s, &c);
        trig[a] = make_float4(c * INV_DS, s * INV_DS, c, s);
    }
    __syncthreads();

    int j  = (blockIdx.x << 3) + (tx & 7);
    int ip = (blockIdx.y << 5) + (tx >> 3);     // i-pair index
    int i0 = ip << 1;
    float xc = fmaf((float)i0 + 0.5f, DX, -1.0f);
    float yc = fmaf((float)j  + 0.5f, DX, -1.0f);

    float fa[16];                     // [pixel0 b0..7, pixel1 b0..7]
#pragma unroll
    for (int b = 0; b < 16; ++b) fa[b] = 0.f;

    const char* gbase = reinterpret_cast<const char*>(g_h);
    const __half2 one2  = __float2half2_rn(1.0f);
    const __half2 zero2 = __float2half2_rn(0.0f);

#pragma unroll 1
    for (int a0 = 0; a0 < N_HALF; a0 += 4) {
        __half2 pF0 = zero2, pF1 = zero2, pF2 = zero2, pF3 = zero2; // pix0 hi-tap
        __half2 pL0 = zero2, pL1 = zero2, pL2 = zero2, pL3 = zero2; // pix0 lo-tap
        __half2 qX0 = zero2, qX1 = zero2, qX2 = zero2, qX3 = zero2; // pix1 w0/w2
        __half2 qY0 = zero2, qY1 = zero2, qY2 = zero2, qY3 = zero2; // pix1 w1

#pragma unroll
        for (int k = 0; k < 4; ++k) {
            int a = a0 + k;
            float4 tg = trig[a];

            // ---- addresses ----
            float uL = fmaf(xc, tg.x, fmaf(yc, tg.y, 511.5f));     // angle a
            float tL = __fadd_rd(uL, 8388608.0f);
            float fiL = tL - 8388608.0f;
            float fL  = uL - fiL;                                   // [0,1)
            unsigned offL = (__float_as_uint(tL) << 9) >> 5;        // base*16

            float uH = fmaf(yc, tg.x, fmaf(-xc, tg.y, 511.5f));    // angle a+360
            float tH = __fadd_rd(uH, 8388608.0f);
            float fiH = tH - 8388608.0f;
            float fH  = uH - fiH;
            unsigned offH = (__float_as_uint(tH) << 9) >> 5;

            // ---- 6 LDG.128 ----
            const uint4* pl = reinterpret_cast<const uint4*>(
                gbase + ((size_t)a << 14) + offL);
            const uint4* ph = reinterpret_cast<const uint4*>(
                gbase + ((size_t)(a + N_HALF) << 14) + offH) - 1;   // base-1
            uint4 b0 = __ldg(pl);       // L: base
            uint4 b1 = __ldg(pl + 1);   // L: base+1
            uint4 b2 = __ldg(pl + 2);   // L: base+2
            uint4 h0 = __ldg(ph);       // H: base-1
            uint4 h1 = __ldg(ph + 1);   // H: base
            uint4 h2 = __ldg(ph + 2);   // H: base+1

            // ---- weights ----
            float gL = fL + tg.z;                   // u(i+1) = u + cos
            float gH = (fH - tg.w) + 1.0f;          // u(i+1) = u - sin, window -1
            float gm1L = gL - 1.0f;
            float w0Ls = fmaxf(-gm1L, 0.0f), w2Ls = fmaxf(gm1L, 0.0f);
            float w1Ls = 1.0f - w0Ls - w2Ls;
            float gm1H = gH - 1.0f;
            float w0Hs = fmaxf(-gm1H, 0.0f), w2Hs = fmaxf(gm1H, 0.0f);
            float w1Hs = 1.0f - w0Hs - w2Hs;

            __half2 f2L = __float2half2_rn(fL), omfL = __hsub2(one2, f2L);
            __half2 f2H = __float2half2_rn(fH), omfH = __hsub2(one2, f2H);
            __half2 w0L = __float2half2_rn(w0Ls), w1L = __float2half2_rn(w1Ls),
                    w2L = __float2half2_rn(w2Ls);
            __half2 w0H = __float2half2_rn(w0Hs), w1H = __float2half2_rn(w1Hs),
                    w2H = __float2half2_rn(w2Hs);

#define H2(v) (*reinterpret_cast<__half2*>(&(v)))
            // pixel0, L angle: (1-fL)*b0 + fL*b1
            pF0 = __hfma2(f2L, H2(b1.x), pF0);  pL0 = __hfma2(omfL, H2(b0.x), pL0);
            pF1 = __hfma2(f2L, H2(b1.y), pF1);  pL1 = __hfma2(omfL, H2(b0.y), pL1);
            pF2 = __hfma2(f2L, H2(b1.z), pF2);  pL2 = __hfma2(omfL, H2(b0.z), pL2);
            pF3 = __hfma2(f2L, H2(b1.w), pF3);  pL3 = __hfma2(omfL, H2(b0.w), pL3);
            // pixel0, H angle: (1-fH)*h1 + fH*h2
            pF0 = __hfma2(f2H, H2(h2.x), pF0);  pL0 = __hfma2(omfH, H2(h1.x), pL0);
            pF1 = __hfma2(f2H, H2(h2.y), pF1);  pL1 = __hfma2(omfH, H2(h1.y), pL1);
            pF2 = __hfma2(f2H, H2(h2.z), pF2);  pL2 = __hfma2(omfH, H2(h1.z), pL2);
            pF3 = __hfma2(f2H, H2(h2.w), pF3);  pL3 = __hfma2(omfH, H2(h1.w), pL3);
            // pixel1, L angle: w0L*b0 + w1L*b1 + w2L*b2
            qX0 = __hfma2(w0L, H2(b0.x), __hfma2(w2L, H2(b2.x), qX0));
            qY0 = __hfma2(w1L, H2(b1.x), qY0);
            qX1 = __hfma2(w0L, H2(b0.y), __hfma2(w2L, H2(b2.y), qX1));
            qY1 = __hfma2(w1L, H2(b1.y), qY1);
            qX2 = __hfma2(w0L, H2(b0.z), __hfma2(w2L, H2(b2.z), qX2));
            qY2 = __hfma2(w1L, H2(b1.z), qY2);
            qX3 = __hfma2(w0L, H2(b0.w), __hfma2(w2L, H2(b2.w), qX3));
            qY3 = __hfma2(w1L, H2(b1.w), qY3);
            // pixel1, H angle: w0H*h0 + w1H*h1 + w2H*h2
            qX0 = __hfma2(w0H, H2(h0.x), __hfma2(w2H, H2(h2.x), qX0));
            qY0 = __hfma2(w1H, H2(h1.x), qY0);
            qX1 = __hfma2(w0H, H2(h0.y), __hfma2(w2H, H2(h2.y), qX1));
            qY1 = __hfma2(w1H, H2(h1.y), qY1);
            qX2 = __hfma2(w0H, H2(h0.z), __hfma2(w2H, H2(h2.z), qX2));
            qY2 = __hfma2(w1H, H2(h1.z), qY2);
            qX3 = __hfma2(w0H, H2(h0.w), __hfma2(w2H, H2(h2.w), qX3));
            qY3 = __hfma2(w1H, H2(h1.w), qY3);
#undef H2
        }

        float2 v;
        __half2 s;
        s = __hadd2(pF0, pL0); v = __half22float2(s); fa[0]  += v.x; fa[1]  += v.y;
        s = __hadd2(pF1, pL1); v = __half22float2(s); fa[2]  += v.x; fa[3]  += v.y;
        s = __hadd2(pF2, pL2); v = __half22float2(s); fa[4]  += v.x; fa[5]  += v.y;
        s = __hadd2(pF3, pL3); v = __half22float2(s); fa[6]  += v.x; fa[7]  += v.y;
        s = __hadd2(qX0, qY0); v = __half22float2(s); fa[8]  += v.x; fa[9]  += v.y;
        s = __hadd2(qX1, qY1); v = __half22float2(s); fa[10] += v.x; fa[11] += v.y;
        s = __hadd2(qX2, qY2); v = __half22float2(s); fa[12] += v.x; fa[13] += v.y;
        s = __hadd2(qX3, qY3); v = __half22float2(s); fa[14] += v.x; fa[15] += v.y;
    }

    int p0 = i0 * WIMG + j;
#pragma unroll
    for (int b = 0; b < NB; ++b) {
        out[b * (HIMG * WIMG) + p0]        = fa[b]     * DTH;
        out[b * (HIMG * WIMG) + p0 + WIMG] = fa[8 + b] * DTH;
    }
}

// ---------------------------------------------------------------------------
extern "C" void kernel_launch(void* const* d_in, const int* in_sizes, int n_in,
                              void* d_out, int out_size) {
    const float* x = (const float*)d_in[0];   // [8,1,720,1024]
    const float* w = (const float*)d_in[1];   // [1,1,1,11]
    float* out = (float*)d_out;               // [8,1,512,512]

    conv_kernel<<<N_ANG, 256>>>(x, w);
    dim3 grid(WIMG / 8, HIMG / 64);           // (64, 8) = 512 CTAs
    bp_kernel<<<grid, 256>>>(out);
}

// round 13
// speedup vs baseline: 1.3483x; 1.0069x over previous
#include <cuda_runtime.h>
#include <cuda_fp16.h>

#define N_ANG 720
#define N_HALF 360
#define N_DET 1024
#define HIMG 512
#define WIMG 512
#define KSZ 11
#define NB 8

// Filtered sinogram, fp16, layout [angle][det_bin][batch0..7] -> 16B per bin.
__device__ __align__(16) __half g_h[N_ANG * N_DET * NB];

// ---------------------------------------------------------------------------
// Stage 1: causal K=11 cross-correlation (unchanged).
// ---------------------------------------------------------------------------
__global__ void __launch_bounds__(256) conv_kernel(const float* __restrict__ x,
                                                   const float* __restrict__ w) {
    int tx = threadIdx.x;
    int a  = blockIdx.x;

    float wk[KSZ];
#pragma unroll
    for (int k = 0; k < KSZ; ++k) wk[k] = __ldg(w + k);

    uint4 out[4];
#pragma unroll
    for (int bp = 0; bp < 4; ++bp) {
        float acc[2][4];
#pragma unroll
        for (int s = 0; s < 2; ++s) {
            int b = bp * 2 + s;
            const float4* xb = reinterpret_cast<const float4*>(
                x + (size_t)b * (N_ANG * N_DET) + (size_t)a * N_DET);
            float win[16];
#pragma unroll
            for (int q = 0; q < 4; ++q) {
                int qi = tx - 3 + q;
                float4 v;
                if (qi >= 0) v = __ldg(xb + qi);
                else         v = make_float4(0.f, 0.f, 0.f, 0.f);
                win[q * 4 + 0] = v.x; win[q * 4 + 1] = v.y;
                win[q * 4 + 2] = v.z; win[q * 4 + 3] = v.w;
            }
#pragma unroll
            for (int di = 0; di < 4; ++di) {
                float acc_ = 0.f;
#pragma unroll
                for (int k = 0; k < KSZ; ++k)
                    acc_ = fmaf(wk[k], win[di + k + 2], acc_);
                acc[s][di] = acc_;
            }
        }
#pragma unroll
        for (int di = 0; di < 4; ++di) {
            __half2 h = __floats2half2_rn(acc[0][di], acc[1][di]);
            reinterpret_cast<unsigned int*>(&out[di])[bp] =
                *reinterpret_cast<unsigned int*>(&h);
        }
    }

    uint4* gp = reinterpret_cast<uint4*>(g_h) + ((size_t)a << 10) + (tx << 2);
#pragma unroll
    for (int di = 0; di < 4; ++di) gp[di] = out[di];
}

// ---------------------------------------------------------------------------
// Stage 2: backprojection. One thread = pixel pair (i, i+1) at one j, all 8
// batches, complementary angle pairs (a, a+360). 3 LDG.128 per angle serve
// both pixels. Pixel1's tap pair is chosen with ALU-pipe SELs:
//   g in [0,2);  sel = g>=1;  lo = sel?b1:b0, hi = sel?b2:b1, f' = g-(sel?1:0)
// then a standard 2-tap — exact reference weights, 8 HFMA2 instead of 12.
// Split half2 accumulators, flushed to fp32 every 4 angle-pairs (8 angles).
// ---------------------------------------------------------------------------
__global__ void __launch_bounds__(256, 3) bp_kernel(float* __restrict__ out) {
    __shared__ float4 trig[N_HALF];   // (cos*256, sin*256, cos, sin)

    const float DTH = 3.14159265358979323846f / (float)N_ANG;
    const float DX  = 2.0f / (float)HIMG;
    const float INV_DS = (float)N_DET / 4.0f;   // 256

    int tx = threadIdx.x;
    for (int a = tx; a < N_HALF; a += blockDim.x) {
        float th = ((float)a + 0.5f) * DTH;
        float s, c;
        sincosf(th, &s, &c);
        trig[a] = make_float4(c * INV_DS, s * INV_DS, c, s);
    }
    __syncthreads();

    int j  = (blockIdx.x << 3) + (tx & 7);
    int ip = (blockIdx.y << 5) + (tx >> 3);     // i-pair index
    int i0 = ip << 1;
    float xc = fmaf((float)i0 + 0.5f, DX, -1.0f);
    float yc = fmaf((float)j  + 0.5f, DX, -1.0f);

    float fa[16];                     // [pixel0 b0..7, pixel1 b0..7]
#pragma unroll
    for (int b = 0; b < 16; ++b) fa[b] = 0.f;

    const char* gbase = reinterpret_cast<const char*>(g_h);
    const __half2 one2  = __float2half2_rn(1.0f);
    const __half2 zero2 = __float2half2_rn(0.0f);

#pragma unroll 1
    for (int a0 = 0; a0 < N_HALF; a0 += 4) {
        __half2 pF0 = zero2, pF1 = zero2, pF2 = zero2, pF3 = zero2; // pix0 hi-tap
        __half2 pL0 = zero2, pL1 = zero2, pL2 = zero2, pL3 = zero2; // pix0 lo-tap
        __half2 qF0 = zero2, qF1 = zero2, qF2 = zero2, qF3 = zero2; // pix1 hi-tap
        __half2 qL0 = zero2, qL1 = zero2, qL2 = zero2, qL3 = zero2; // pix1 lo-tap

#pragma unroll
        for (int k = 0; k < 4; ++k) {
            int a = a0 + k;
            float4 tg = trig[a];

            // ---- addresses ----
            float uL = fmaf(xc, tg.x, fmaf(yc, tg.y, 511.5f));     // angle a
            float tL = __fadd_rd(uL, 8388608.0f);
            float fiL = tL - 8388608.0f;
            float fL  = uL - fiL;                                   // [0,1)
            unsigned offL = (__float_as_uint(tL) << 9) >> 5;        // base*16

            float uH = fmaf(yc, tg.x, fmaf(-xc, tg.y, 511.5f));    // angle a+360
            float tH = __fadd_rd(uH, 8388608.0f);
            float fiH = tH - 8388608.0f;
            float fH  = uH - fiH;
            unsigned offH = (__float_as_uint(tH) << 9) >> 5;

            // ---- 6 LDG.128 ----
            const uint4* pl = reinterpret_cast<const uint4*>(
                gbase + ((size_t)a << 14) + offL);
            const uint4* ph = reinterpret_cast<const uint4*>(
                gbase + ((size_t)(a + N_HALF) << 14) + offH) - 1;   // base-1
            uint4 b0 = __ldg(pl);       // L: base
            uint4 b1 = __ldg(pl + 1);   // L: base+1
            uint4 b2 = __ldg(pl + 2);   // L: base+2
            uint4 h0 = __ldg(ph);       // H: base-1
            uint4 h1 = __ldg(ph + 1);   // H: base
            uint4 h2 = __ldg(ph + 2);   // H: base+1

            // ---- pixel1 tap selection (ALU pipe) ----
            float gL = fL + tg.z;                  // u(i+1) = u + cos, [0,2)
            bool  sL = gL >= 1.0f;
            float fpL = sL ? (gL - 1.0f) : gL;
            unsigned cL0x = sL ? b1.x : b0.x, cL1x = sL ? b2.x : b1.x;
            unsigned cL0y = sL ? b1.y : b0.y, cL1y = sL ? b2.y : b1.y;
            unsigned cL0z = sL ? b1.z : b0.z, cL1z = sL ? b2.z : b1.z;
            unsigned cL0w = sL ? b1.w : b0.w, cL1w = sL ? b2.w : b1.w;

            float gH = (fH - tg.w) + 1.0f;         // u(i+1) = u - sin, win -1
            bool  sH = gH >= 1.0f;
            float fpH = sH ? (gH - 1.0f) : gH;
            unsigned cH0x = sH ? h1.x : h0.x, cH1x = sH ? h2.x : h1.x;
            unsigned cH0y = sH ? h1.y : h0.y, cH1y = sH ? h2.y : h1.y;
            unsigned cH0z = sH ? h1.z : h0.z, cH1z = sH ? h2.z : h1.z;
            unsigned cH0w = sH ? h1.w : h0.w, cH1w = sH ? h2.w : h1.w;

            __half2 f2L = __float2half2_rn(fL),  omfL = __hsub2(one2, f2L);
            __half2 f2H = __float2half2_rn(fH),  omfH = __hsub2(one2, f2H);
            __half2 g2L = __float2half2_rn(fpL), omgL = __hsub2(one2, g2L);
            __half2 g2H = __float2half2_rn(fpH), omgH = __hsub2(one2, g2H);

#define H2(v) (*reinterpret_cast<__half2*>(&(v)))
            // pixel0, L angle: (1-fL)*b0 + fL*b1
            pF0 = __hfma2(f2L, H2(b1.x), pF0);  pL0 = __hfma2(omfL, H2(b0.x), pL0);
            pF1 = __hfma2(f2L, H2(b1.y), pF1);  pL1 = __hfma2(omfL, H2(b0.y), pL1);
            pF2 = __hfma2(f2L, H2(b1.z), pF2);  pL2 = __hfma2(omfL, H2(b0.z), pL2);
            pF3 = __hfma2(f2L, H2(b1.w), pF3);  pL3 = __hfma2(omfL, H2(b0.w), pL3);
            // pixel0, H angle: (1-fH)*h1 + fH*h2
            pF0 = __hfma2(f2H, H2(h2.x), pF0);  pL0 = __hfma2(omfH, H2(h1.x), pL0);
            pF1 = __hfma2(f2H, H2(h2.y), pF1);  pL1 = __hfma2(omfH, H2(h1.y), pL1);
            pF2 = __hfma2(f2H, H2(h2.z), pF2);  pL2 = __hfma2(omfH, H2(h1.z), pL2);
            pF3 = __hfma2(f2H, H2(h2.w), pF3);  pL3 = __hfma2(omfH, H2(h1.w), pL3);
            // pixel1, L angle: (1-fpL)*cL0 + fpL*cL1
            qF0 = __hfma2(g2L, H2(cL1x), qF0);  qL0 = __hfma2(omgL, H2(cL0x), qL0);
            qF1 = __hfma2(g2L, H2(cL1y), qF1);  qL1 = __hfma2(omgL, H2(cL0y), qL1);
            qF2 = __hfma2(g2L, H2(cL1z), qF2);  qL2 = __hfma2(omgL, H2(cL0z), qL2);
            qF3 = __hfma2(g2L, H2(cL1w), qF3);  qL3 = __hfma2(omgL, H2(cL0w), qL3);
            // pixel1, H angle: (1-fpH)*cH0 + fpH*cH1
            qF0 = __hfma2(g2H, H2(cH1x), qF0);  qL0 = __hfma2(omgH, H2(cH0x), qL0);
            qF1 = __hfma2(g2H, H2(cH1y), qF1);  qL1 = __hfma2(omgH, H2(cH0y), qL1);
            qF2 = __hfma2(g2H, H2(cH1z), qF2);  qL2 = __hfma2(omgH, H2(cH0z), qL2);
            qF3 = __hfma2(g2H, H2(cH1w), qF3);  qL3 = __hfma2(omgH, H2(cH0w), qL3);
#undef H2
        }

        float2 v;
        __half2 s;
        s = __hadd2(pF0, pL0); v = __half22float2(s); fa[0]  += v.x; fa[1]  += v.y;
        s = __hadd2(pF1, pL1); v = __half22float2(s); fa[2]  += v.x; fa[3]  += v.y;
        s = __hadd2(pF2, pL2); v = __half22float2(s); fa[4]  += v.x; fa[5]  += v.y;
        s = __hadd2(pF3, pL3); v = __half22float2(s); fa[6]  += v.x; fa[7]  += v.y;
        s = __hadd2(qF0, qL0); v = __half22float2(s); fa[8]  += v.x; fa[9]  += v.y;
        s = __hadd2(qF1, qL1); v = __half22float2(s); fa[10] += v.x; fa[11] += v.y;
        s = __hadd2(qF2, qL2); v = __half22float2(s); fa[12] += v.x; fa[13] += v.y;
        s = __hadd2(qF3, qL3); v = __half22float2(s); fa[14] += v.x; fa[15] += v.y;
    }

    int p0 = i0 * WIMG + j;
#pragma unroll
    for (int b = 0; b < NB; ++b) {
        out[b * (HIMG * WIMG) + p0]        = fa[b]     * DTH;
        out[b * (HIMG * WIMG) + p0 + WIMG] = fa[8 + b] * DTH;
    }
}

// ---------------------------------------------------------------------------
extern "C" void kernel_launch(void* const* d_in, const int* in_sizes, int n_in,
                              void* d_out, int out_size) {
    const float* x = (const float*)d_in[0];   // [8,1,720,1024]
    const float* w = (const float*)d_in[1];   // [1,1,1,11]
    float* out = (float*)d_out;               // [8,1,512,512]

    conv_kernel<<<N_ANG, 256>>>(x, w);
    dim3 grid(WIMG / 8, HIMG / 64);           // (64, 8) = 512 CTAs
    bp_kernel<<<grid, 256>>>(out);
}

// round 14
// speedup vs baseline: 1.6046x; 1.1901x over previous
#include <cuda_runtime.h>
#include <cuda_fp16.h>

#define N_ANG 720
#define N_HALF 360
#define N_DET 1024
#define HIMG 512
#define WIMG 512
#define KSZ 11
#define NB 8

// Filtered sinogram, fp16, layout [angle][det_bin][batch0..7] -> 16B per bin.
__device__ __align__(16) __half g_h[N_ANG * N_DET * NB];

// ---------------------------------------------------------------------------
// Stage 1: causal K=11 cross-correlation (unchanged).
// ---------------------------------------------------------------------------
__global__ void __launch_bounds__(256) conv_kernel(const float* __restrict__ x,
                                                   const float* __restrict__ w) {
    int tx = threadIdx.x;
    int a  = blockIdx.x;

    float wk[KSZ];
#pragma unroll
    for (int k = 0; k < KSZ; ++k) wk[k] = __ldg(w + k);

    uint4 out[4];
#pragma unroll
    for (int bp = 0; bp < 4; ++bp) {
        float acc[2][4];
#pragma unroll
        for (int s = 0; s < 2; ++s) {
            int b = bp * 2 + s;
            const float4* xb = reinterpret_cast<const float4*>(
                x + (size_t)b * (N_ANG * N_DET) + (size_t)a * N_DET);
            float win[16];
#pragma unroll
            for (int q = 0; q < 4; ++q) {
                int qi = tx - 3 + q;
                float4 v;
                if (qi >= 0) v = __ldg(xb + qi);
                else         v = make_float4(0.f, 0.f, 0.f, 0.f);
                win[q * 4 + 0] = v.x; win[q * 4 + 1] = v.y;
                win[q * 4 + 2] = v.z; win[q * 4 + 3] = v.w;
            }
#pragma unroll
            for (int di = 0; di < 4; ++di) {
                float acc_ = 0.f;
#pragma unroll
                for (int k = 0; k < KSZ; ++k)
                    acc_ = fmaf(wk[k], win[di + k + 2], acc_);
                acc[s][di] = acc_;
            }
        }
#pragma unroll
        for (int di = 0; di < 4; ++di) {
            __half2 h = __floats2half2_rn(acc[0][di], acc[1][di]);
            reinterpret_cast<unsigned int*>(&out[di])[bp] =
                *reinterpret_cast<unsigned int*>(&h);
        }
    }

    uint4* gp = reinterpret_cast<uint4*>(g_h) + ((size_t)a << 10) + (tx << 2);
#pragma unroll
    for (int di = 0; di < 4; ++di) gp[di] = out[di];
}

// ---------------------------------------------------------------------------
// Stage 2: backprojection. One thread = pixel pair (i, i+1) at one j, all 8
// batches, complementary angle pairs (a, a+360); 3 LDG.128/angle serve both
// pixels; pixel1 taps chosen by ALU SELs. MERGED half2 accumulators (8, not
// 16) -> fits 64 regs -> occ 4/SM -> 512-CTA grid runs as ONE wave (592 cap).
// Flushed to fp32 every 4 angle-pairs (8 angles).
// ---------------------------------------------------------------------------
__global__ void __launch_bounds__(256, 4) bp_kernel(float* __restrict__ out) {
    __shared__ float4 trig[N_HALF];   // (cos*256, sin*256, cos, sin)

    const float DTH = 3.14159265358979323846f / (float)N_ANG;
    const float DX  = 2.0f / (float)HIMG;
    const float INV_DS = (float)N_DET / 4.0f;   // 256

    int tx = threadIdx.x;
    for (int a = tx; a < N_HALF; a += blockDim.x) {
        float th = ((float)a + 0.5f) * DTH;
        float s, c;
        sincosf(th, &s, &c);
        trig[a] = make_float4(c * INV_DS, s * INV_DS, c, s);
    }
    __syncthreads();

    int j  = (blockIdx.x << 3) + (tx & 7);
    int ip = (blockIdx.y << 5) + (tx >> 3);     // i-pair index
    int i0 = ip << 1;
    float xc = fmaf((float)i0 + 0.5f, DX, -1.0f);
    float yc = fmaf((float)j  + 0.5f, DX, -1.0f);

    float fa[16];                     // [pixel0 b0..7, pixel1 b0..7]
#pragma unroll
    for (int b = 0; b < 16; ++b) fa[b] = 0.f;

    const char* gbase = reinterpret_cast<const char*>(g_h);
    const __half2 one2  = __float2half2_rn(1.0f);
    const __half2 zero2 = __float2half2_rn(0.0f);

#pragma unroll 1
    for (int a0 = 0; a0 < N_HALF; a0 += 4) {
        __half2 p0 = zero2, p1 = zero2, p2 = zero2, p3 = zero2;   // pixel0
        __half2 q0 = zero2, q1 = zero2, q2 = zero2, q3 = zero2;   // pixel1

#pragma unroll
        for (int k = 0; k < 4; ++k) {
            int a = a0 + k;
            float4 tg = trig[a];

            // ---- addresses ----
            float uL = fmaf(xc, tg.x, fmaf(yc, tg.y, 511.5f));     // angle a
            float tL = __fadd_rd(uL, 8388608.0f);
            float fiL = tL - 8388608.0f;
            float fL  = uL - fiL;                                   // [0,1)
            unsigned offL = (__float_as_uint(tL) << 9) >> 5;        // base*16

            float uH = fmaf(yc, tg.x, fmaf(-xc, tg.y, 511.5f));    // angle a+360
            float tH = __fadd_rd(uH, 8388608.0f);
            float fiH = tH - 8388608.0f;
            float fH  = uH - fiH;
            unsigned offH = (__float_as_uint(tH) << 9) >> 5;

            // ---- 6 LDG.128 ----
            const uint4* pl = reinterpret_cast<const uint4*>(
                gbase + ((size_t)a << 14) + offL);
            const uint4* ph = reinterpret_cast<const uint4*>(
                gbase + ((size_t)(a + N_HALF) << 14) + offH) - 1;   // base-1
            uint4 b0 = __ldg(pl);       // L: base
            uint4 b1 = __ldg(pl + 1);   // L: base+1
            uint4 b2 = __ldg(pl + 2);   // L: base+2
            uint4 h0 = __ldg(ph);       // H: base-1
            uint4 h1 = __ldg(ph + 1);   // H: base
            uint4 h2 = __ldg(ph + 2);   // H: base+1

            // ---- pixel1 tap selection (ALU pipe) ----
            float gL = fL + tg.z;                  // u(i+1) = u + cos, [0,2)
            bool  sL = gL >= 1.0f;
            float fpL = sL ? (gL - 1.0f) : gL;
            unsigned cL0x = sL ? b1.x : b0.x, cL1x = sL ? b2.x : b1.x;
            unsigned cL0y = sL ? b1.y : b0.y, cL1y = sL ? b2.y : b1.y;
            unsigned cL0z = sL ? b1.z : b0.z, cL1z = sL ? b2.z : b1.z;
            unsigned cL0w = sL ? b1.w : b0.w, cL1w = sL ? b2.w : b1.w;

            float gH = (fH - tg.w) + 1.0f;         // u(i+1) = u - sin, win -1
            bool  sH = gH >= 1.0f;
            float fpH = sH ? (gH - 1.0f) : gH;
            unsigned cH0x = sH ? h1.x : h0.x, cH1x = sH ? h2.x : h1.x;
            unsigned cH0y = sH ? h1.y : h0.y, cH1y = sH ? h2.y : h1.y;
            unsigned cH0z = sH ? h1.z : h0.z, cH1z = sH ? h2.z : h1.z;
            unsigned cH0w = sH ? h1.w : h0.w, cH1w = sH ? h2.w : h1.w;

            __half2 f2L = __float2half2_rn(fL),  omfL = __hsub2(one2, f2L);
            __half2 f2H = __float2half2_rn(fH),  omfH = __hsub2(one2, f2H);
            __half2 g2L = __float2half2_rn(fpL), omgL = __hsub2(one2, g2L);
            __half2 g2H = __float2half2_rn(fpH), omgH = __hsub2(one2, g2H);

#define H2(v) (*reinterpret_cast<__half2*>(&(v)))
            // pixel0, L angle then H angle (merged accumulators)
            p0 = __hfma2(f2L, H2(b1.x), __hfma2(omfL, H2(b0.x), p0));
            p1 = __hfma2(f2L, H2(b1.y), __hfma2(omfL, H2(b0.y), p1));
            p2 = __hfma2(f2L, H2(b1.z), __hfma2(omfL, H2(b0.z), p2));
            p3 = __hfma2(f2L, H2(b1.w), __hfma2(omfL, H2(b0.w), p3));
            p0 = __hfma2(f2H, H2(h2.x), __hfma2(omfH, H2(h1.x), p0));
            p1 = __hfma2(f2H, H2(h2.y), __hfma2(omfH, H2(h1.y), p1));
            p2 = __hfma2(f2H, H2(h2.z), __hfma2(omfH, H2(h1.z), p2));
            p3 = __hfma2(f2H, H2(h2.w), __hfma2(omfH, H2(h1.w), p3));
            // pixel1, L angle then H angle
            q0 = __hfma2(g2L, H2(cL1x), __hfma2(omgL, H2(cL0x), q0));
            q1 = __hfma2(g2L, H2(cL1y), __hfma2(omgL, H2(cL0y), q1));
            q2 = __hfma2(g2L, H2(cL1z), __hfma2(omgL, H2(cL0z), q2));
            q3 = __hfma2(g2L, H2(cL1w), __hfma2(omgL, H2(cL0w), q3));
            q0 = __hfma2(g2H, H2(cH1x), __hfma2(omgH, H2(cH0x), q0));
            q1 = __hfma2(g2H, H2(cH1y), __hfma2(omgH, H2(cH0y), q1));
            q2 = __hfma2(g2H, H2(cH1z), __hfma2(omgH, H2(cH0z), q2));
            q3 = __hfma2(g2H, H2(cH1w), __hfma2(omgH, H2(cH0w), q3));
#undef H2
        }

        float2 v;
        v = __half22float2(p0); fa[0]  += v.x; fa[1]  += v.y;
        v = __half22float2(p1); fa[2]  += v.x; fa[3]  += v.y;
        v = __half22float2(p2); fa[4]  += v.x; fa[5]  += v.y;
        v = __half22float2(p3); fa[6]  += v.x; fa[7]  += v.y;
        v = __half22float2(q0); fa[8]  += v.x; fa[9]  += v.y;
        v = __half22float2(q1); fa[10] += v.x; fa[11] += v.y;
        v = __half22float2(q2); fa[12] += v.x; fa[13] += v.y;
        v = __half22float2(q3); fa[14] += v.x; fa[15] += v.y;
    }

    int p0i = i0 * WIMG + j;
#pragma unroll
    for (int b = 0; b < NB; ++b) {
        out[b * (HIMG * WIMG) + p0i]        = fa[b]     * DTH;
        out[b * (HIMG * WIMG) + p0i + WIMG] = fa[8 + b] * DTH;
    }
}

// ---------------------------------------------------------------------------
extern "C" void kernel_launch(void* const* d_in, const int* in_sizes, int n_in,
                              void* d_out, int out_size) {
    const float* x = (const float*)d_in[0];   // [8,1,720,1024]
    const float* w = (const float*)d_in[1];   // [1,1,1,11]
    float* out = (float*)d_out;               // [8,1,512,512]

    conv_kernel<<<N_ANG, 256>>>(x, w);
    dim3 grid(WIMG / 8, HIMG / 64);           // (64, 8) = 512 CTAs
    bp_kernel<<<grid, 256>>>(out);
}

// round 15
// speedup vs baseline: 1.8103x; 1.1282x over previous
#include <cuda_runtime.h>
#include <cuda_fp16.h>

#define N_ANG 720
#define N_HALF 360
#define N_DET 1024
#define HIMG 512
#define WIMG 512
#define KSZ 11
#define NB 8

// Filtered sinogram, fp16, layout [angle][det_bin][batch0..7] -> 16B per bin.
__device__ __align__(16) __half g_h[N_ANG * N_DET * NB];

// ---------------------------------------------------------------------------
// Stage 1: causal K=11 cross-correlation (unchanged).
// ---------------------------------------------------------------------------
__global__ void __launch_bounds__(256) conv_kernel(const float* __restrict__ x,
                                                   const float* __restrict__ w) {
    int tx = threadIdx.x;
    int a  = blockIdx.x;

    float wk[KSZ];
#pragma unroll
    for (int k = 0; k < KSZ; ++k) wk[k] = __ldg(w + k);

    uint4 out[4];
#pragma unroll
    for (int bp = 0; bp < 4; ++bp) {
        float acc[2][4];
#pragma unroll
        for (int s = 0; s < 2; ++s) {
            int b = bp * 2 + s;
            const float4* xb = reinterpret_cast<const float4*>(
                x + (size_t)b * (N_ANG * N_DET) + (size_t)a * N_DET);
            float win[16];
#pragma unroll
            for (int q = 0; q < 4; ++q) {
                int qi = tx - 3 + q;
                float4 v;
                if (qi >= 0) v = __ldg(xb + qi);
                else         v = make_float4(0.f, 0.f, 0.f, 0.f);
                win[q * 4 + 0] = v.x; win[q * 4 + 1] = v.y;
                win[q * 4 + 2] = v.z; win[q * 4 + 3] = v.w;
            }
#pragma unroll
            for (int di = 0; di < 4; ++di) {
                float acc_ = 0.f;
#pragma unroll
                for (int k = 0; k < KSZ; ++k)
                    acc_ = fmaf(wk[k], win[di + k + 2], acc_);
                acc[s][di] = acc_;
            }
        }
#pragma unroll
        for (int di = 0; di < 4; ++di) {
            __half2 h = __floats2half2_rn(acc[0][di], acc[1][di]);
            reinterpret_cast<unsigned int*>(&out[di])[bp] =
                *reinterpret_cast<unsigned int*>(&h);
        }
    }

    uint4* gp = reinterpret_cast<uint4*>(g_h) + ((size_t)a << 10) + (tx << 2);
#pragma unroll
    for (int di = 0; di < 4; ++di) gp[di] = out[di];
}

// ---------------------------------------------------------------------------
// Stage 2: backprojection. One thread = pixel pair (i, i+1) at one j, all 8
// batches, complementary angle pairs (a, a+360); 3 LDG.128/angle serve both
// pixels; pixel1 taps chosen by ALU SELs; merged half2 accumulators.
// 128-THREAD CTAs (8j x 16 i-pairs), grid=1024: at 64 regs the cap is 8
// CTAs/SM, so 1024 CTAs spread max-7 vs avg-6.92 per SM -> ~1% intra-wave
// imbalance (vs 15% at 512x256). Flushed to fp32 every 4 angle-pairs.
// ---------------------------------------------------------------------------
__global__ void __launch_bounds__(128, 8) bp_kernel(float* __restrict__ out) {
    __shared__ float4 trig[N_HALF];   // (cos*256, sin*256, cos, sin)

    const float DTH = 3.14159265358979323846f / (float)N_ANG;
    const float DX  = 2.0f / (float)HIMG;
    const float INV_DS = (float)N_DET / 4.0f;   // 256

    int tx = threadIdx.x;
    for (int a = tx; a < N_HALF; a += blockDim.x) {
        float th = ((float)a + 0.5f) * DTH;
        float s, c;
        sincosf(th, &s, &c);
        trig[a] = make_float4(c * INV_DS, s * INV_DS, c, s);
    }
    __syncthreads();

    int j  = (blockIdx.x << 3) + (tx & 7);
    int ip = (blockIdx.y << 4) + (tx >> 3);     // i-pair index (16 per CTA)
    int i0 = ip << 1;
    float xc = fmaf((float)i0 + 0.5f, DX, -1.0f);
    float yc = fmaf((float)j  + 0.5f, DX, -1.0f);

    float fa[16];                     // [pixel0 b0..7, pixel1 b0..7]
#pragma unroll
    for (int b = 0; b < 16; ++b) fa[b] = 0.f;

    const char* gbase = reinterpret_cast<const char*>(g_h);
    const __half2 one2  = __float2half2_rn(1.0f);
    const __half2 zero2 = __float2half2_rn(0.0f);

#pragma unroll 1
    for (int a0 = 0; a0 < N_HALF; a0 += 4) {
        __half2 p0 = zero2, p1 = zero2, p2 = zero2, p3 = zero2;   // pixel0
        __half2 q0 = zero2, q1 = zero2, q2 = zero2, q3 = zero2;   // pixel1

#pragma unroll
        for (int k = 0; k < 4; ++k) {
            int a = a0 + k;
            float4 tg = trig[a];

            // ---- addresses ----
            float uL = fmaf(xc, tg.x, fmaf(yc, tg.y, 511.5f));     // angle a
            float tL = __fadd_rd(uL, 8388608.0f);
            float fiL = tL - 8388608.0f;
            float fL  = uL - fiL;                                   // [0,1)
            unsigned offL = (__float_as_uint(tL) << 9) >> 5;        // base*16

            float uH = fmaf(yc, tg.x, fmaf(-xc, tg.y, 511.5f));    // angle a+360
            float tH = __fadd_rd(uH, 8388608.0f);
            float fiH = tH - 8388608.0f;
            float fH  = uH - fiH;
            unsigned offH = (__float_as_uint(tH) << 9) >> 5;

            // ---- 6 LDG.128 ----
            const uint4* pl = reinterpret_cast<const uint4*>(
                gbase + ((size_t)a << 14) + offL);
            const uint4* ph = reinterpret_cast<const uint4*>(
                gbase + ((size_t)(a + N_HALF) << 14) + offH) - 1;   // base-1
            uint4 b0 = __ldg(pl);       // L: base
            uint4 b1 = __ldg(pl + 1);   // L: base+1
            uint4 b2 = __ldg(pl + 2);   // L: base+2
            uint4 h0 = __ldg(ph);       // H: base-1
            uint4 h1 = __ldg(ph + 1);   // H: base
            uint4 h2 = __ldg(ph + 2);   // H: base+1

            // ---- pixel1 tap selection (ALU pipe) ----
            float gL = fL + tg.z;                  // u(i+1) = u + cos, [0,2)
            bool  sL = gL >= 1.0f;
            float fpL = sL ? (gL - 1.0f) : gL;
            unsigned cL0x = sL ? b1.x : b0.x, cL1x = sL ? b2.x : b1.x;
            unsigned cL0y = sL ? b1.y : b0.y, cL1y = sL ? b2.y : b1.y;
            unsigned cL0z = sL ? b1.z : b0.z, cL1z = sL ? b2.z : b1.z;
            unsigned cL0w = sL ? b1.w : b0.w, cL1w = sL ? b2.w : b1.w;

            float gH = (fH - tg.w) + 1.0f;         // u(i+1) = u - sin, win -1
            bool  sH = gH >= 1.0f;
            float fpH = sH ? (gH - 1.0f) : gH;
            unsigned cH0x = sH ? h1.x : h0.x, cH1x = sH ? h2.x : h1.x;
            unsigned cH0y = sH ? h1.y : h0.y, cH1y = sH ? h2.y : h1.y;
            unsigned cH0z = sH ? h1.z : h0.z, cH1z = sH ? h2.z : h1.z;
            unsigned cH0w = sH ? h1.w : h0.w, cH1w = sH ? h2.w : h1.w;

            __half2 f2L = __float2half2_rn(fL),  omfL = __hsub2(one2, f2L);
            __half2 f2H = __float2half2_rn(fH),  omfH = __hsub2(one2, f2H);
            __half2 g2L = __float2half2_rn(fpL), omgL = __hsub2(one2, g2L);
            __half2 g2H = __float2half2_rn(fpH), omgH = __hsub2(one2, g2H);

#define H2(v) (*reinterpret_cast<__half2*>(&(v)))
            // pixel0, L angle then H angle (merged accumulators)
            p0 = __hfma2(f2L, H2(b1.x), __hfma2(omfL, H2(b0.x), p0));
            p1 = __hfma2(f2L, H2(b1.y), __hfma2(omfL, H2(b0.y), p1));
            p2 = __hfma2(f2L, H2(b1.z), __hfma2(omfL, H2(b0.z), p2));
            p3 = __hfma2(f2L, H2(b1.w), __hfma2(omfL, H2(b0.w), p3));
            p0 = __hfma2(f2H, H2(h2.x), __hfma2(omfH, H2(h1.x), p0));
            p1 = __hfma2(f2H, H2(h2.y), __hfma2(omfH, H2(h1.y), p1));
            p2 = __hfma2(f2H, H2(h2.z), __hfma2(omfH, H2(h1.z), p2));
            p3 = __hfma2(f2H, H2(h2.w), __hfma2(omfH, H2(h1.w), p3));
            // pixel1, L angle then H angle
            q0 = __hfma2(g2L, H2(cL1x), __hfma2(omgL, H2(cL0x), q0));
            q1 = __hfma2(g2L, H2(cL1y), __hfma2(omgL, H2(cL0y), q1));
            q2 = __hfma2(g2L, H2(cL1z), __hfma2(omgL, H2(cL0z), q2));
            q3 = __hfma2(g2L, H2(cL1w), __hfma2(omgL, H2(cL0w), q3));
            q0 = __hfma2(g2H, H2(cH1x), __hfma2(omgH, H2(cH0x), q0));
            q1 = __hfma2(g2H, H2(cH1y), __hfma2(omgH, H2(cH0y), q1));
            q2 = __hfma2(g2H, H2(cH1z), __hfma2(omgH, H2(cH0z), q2));
            q3 = __hfma2(g2H, H2(cH1w), __hfma2(omgH, H2(cH0w), q3));
#undef H2
        }

        float2 v;
        v = __half22float2(p0); fa[0]  += v.x; fa[1]  += v.y;
        v = __half22float2(p1); fa[2]  += v.x; fa[3]  += v.y;
        v = __half22float2(p2); fa[4]  += v.x; fa[5]  += v.y;
        v = __half22float2(p3); fa[6]  += v.x; fa[7]  += v.y;
        v = __half22float2(q0); fa[8]  += v.x; fa[9]  += v.y;
        v = __half22float2(q1); fa[10] += v.x; fa[11] += v.y;
        v = __half22float2(q2); fa[12] += v.x; fa[13] += v.y;
        v = __half22float2(q3); fa[14] += v.x; fa[15] += v.y;
    }

    int p0i = i0 * WIMG + j;
#pragma unroll
    for (int b = 0; b < NB; ++b) {
        out[b * (HIMG * WIMG) + p0i]        = fa[b]     * DTH;
        out[b * (HIMG * WIMG) + p0i + WIMG] = fa[8 + b] * DTH;
    }
}

// ---------------------------------------------------------------------------
extern "C" void kernel_launch(void* const* d_in, const int* in_sizes, int n_in,
                              void* d_out, int out_size) {
    const float* x = (const float*)d_in[0];   // [8,1,720,1024]
    const float* w = (const float*)d_in[1];   // [1,1,1,11]
    float* out = (float*)d_out;               // [8,1,512,512]

    conv_kernel<<<N_ANG, 256>>>(x, w);
    dim3 grid(WIMG / 8, HIMG / 32);           // (64, 16) = 1024 CTAs of 128
    bp_kernel<<<grid, 128>>>(out);
}

// round 16
// speedup vs baseline: 1.8300x; 1.0109x over previous
#include <cuda_runtime.h>
#include <cuda_fp16.h>

#define N_ANG 720
#define N_HALF 360
#define N_DET 1024
#define HIMG 512
#define WIMG 512
#define KSZ 11
#define NB 8

// Filtered sinogram, fp16, layout [angle][det_bin][batch0..7] -> 16B per bin.
__device__ __align__(16) __half g_h[N_ANG * N_DET * NB];

// ---------------------------------------------------------------------------
// Stage 1: causal K=11 cross-correlation (unchanged).
// ---------------------------------------------------------------------------
__global__ void __launch_bounds__(256) conv_kernel(const float* __restrict__ x,
                                                   const float* __restrict__ w) {
    int tx = threadIdx.x;
    int a  = blockIdx.x;

    float wk[KSZ];
#pragma unroll
    for (int k = 0; k < KSZ; ++k) wk[k] = __ldg(w + k);

    uint4 out[4];
#pragma unroll
    for (int bp = 0; bp < 4; ++bp) {
        float acc[2][4];
#pragma unroll
        for (int s = 0; s < 2; ++s) {
            int b = bp * 2 + s;
            const float4* xb = reinterpret_cast<const float4*>(
                x + (size_t)b * (N_ANG * N_DET) + (size_t)a * N_DET);
            float win[16];
#pragma unroll
            for (int q = 0; q < 4; ++q) {
                int qi = tx - 3 + q;
                float4 v;
                if (qi >= 0) v = __ldg(xb + qi);
                else         v = make_float4(0.f, 0.f, 0.f, 0.f);
                win[q * 4 + 0] = v.x; win[q * 4 + 1] = v.y;
                win[q * 4 + 2] = v.z; win[q * 4 + 3] = v.w;
            }
#pragma unroll
            for (int di = 0; di < 4; ++di) {
                float acc_ = 0.f;
#pragma unroll
                for (int k = 0; k < KSZ; ++k)
                    acc_ = fmaf(wk[k], win[di + k + 2], acc_);
                acc[s][di] = acc_;
            }
        }
#pragma unroll
        for (int di = 0; di < 4; ++di) {
            __half2 h = __floats2half2_rn(acc[0][di], acc[1][di]);
            reinterpret_cast<unsigned int*>(&out[di])[bp] =
                *reinterpret_cast<unsigned int*>(&h);
        }
    }

    uint4* gp = reinterpret_cast<uint4*>(g_h) + ((size_t)a << 10) + (tx << 2);
#pragma unroll
    for (int di = 0; di < 4; ++di) gp[di] = out[di];
}

// ---------------------------------------------------------------------------
// Stage 2: backprojection. One thread = pixel pair (i, i+1) at one j, all 8
// batches, complementary angle pairs (a, a+360); 3 LDG.128/angle serve both
// pixels. Pixel1 interp via the |g-1| identity: taps = (b1, side) with
//   side = (g<1) ? b0 : b2,  ws = |g-1|,  w1 = 1-|g-1|
// -> 4 SELs instead of 8 and cheaper weight math (exact reference weights).
// Merged half2 accumulators, 128-thr CTAs (single balanced wave at occ 8).
// ---------------------------------------------------------------------------
__global__ void __launch_bounds__(128, 8) bp_kernel(float* __restrict__ out) {
    __shared__ float4 trig[N_HALF];   // (cos*256, sin*256, cos, 1-sin)

    const float DTH = 3.14159265358979323846f / (float)N_ANG;
    const float DX  = 2.0f / (float)HIMG;
    const float INV_DS = (float)N_DET / 4.0f;   // 256

    int tx = threadIdx.x;
    for (int a = tx; a < N_HALF; a += blockDim.x) {
        float th = ((float)a + 0.5f) * DTH;
        float s, c;
        sincosf(th, &s, &c);
        trig[a] = make_float4(c * INV_DS, s * INV_DS, c, 1.0f - s);
    }
    __syncthreads();

    int j  = (blockIdx.x << 3) + (tx & 7);
    int ip = (blockIdx.y << 4) + (tx >> 3);     // i-pair index (16 per CTA)
    int i0 = ip << 1;
    float xc = fmaf((float)i0 + 0.5f, DX, -1.0f);
    float yc = fmaf((float)j  + 0.5f, DX, -1.0f);

    float fa[16];                     // [pixel0 b0..7, pixel1 b0..7]
#pragma unroll
    for (int b = 0; b < 16; ++b) fa[b] = 0.f;

    const char* gbase = reinterpret_cast<const char*>(g_h);
    const __half2 one2  = __float2half2_rn(1.0f);
    const __half2 zero2 = __float2half2_rn(0.0f);

#pragma unroll 1
    for (int a0 = 0; a0 < N_HALF; a0 += 4) {
        __half2 p0 = zero2, p1 = zero2, p2 = zero2, p3 = zero2;   // pixel0
        __half2 q0 = zero2, q1 = zero2, q2 = zero2, q3 = zero2;   // pixel1

#pragma unroll
        for (int k = 0; k < 4; ++k) {
            int a = a0 + k;
            float4 tg = trig[a];

            // ---- addresses ----
            float uL = fmaf(xc, tg.x, fmaf(yc, tg.y, 511.5f));     // angle a
            float tL = __fadd_rd(uL, 8388608.0f);
            float fiL = tL - 8388608.0f;
            float fL  = uL - fiL;                                   // [0,1)
            unsigned offL = (__float_as_uint(tL) << 9) >> 5;        // base*16

            float uH = fmaf(yc, tg.x, fmaf(-xc, tg.y, 511.5f));    // angle a+360
            float tH = __fadd_rd(uH, 8388608.0f);
            float fiH = tH - 8388608.0f;
            float fH  = uH - fiH;
            unsigned offH = (__float_as_uint(tH) << 9) >> 5;

            // ---- 6 LDG.128 ----
            const uint4* pl = reinterpret_cast<const uint4*>(
                gbase + ((size_t)a << 14) + offL);
            const uint4* ph = reinterpret_cast<const uint4*>(
                gbase + ((size_t)(a + N_HALF) << 14) + offH) - 1;   // base-1
            uint4 b0 = __ldg(pl);       // L: base
            uint4 b1 = __ldg(pl + 1);   // L: base+1
            uint4 b2 = __ldg(pl + 2);   // L: base+2
            uint4 h0 = __ldg(ph);       // H: base-1
            uint4 h1 = __ldg(ph + 1);   // H: base
            uint4 h2 = __ldg(ph + 2);   // H: base+1

            // ---- pixel1 side-tap selection (4 SELs per angle) ----
            float gL = fL + tg.z;                  // u(i+1)-base, [0,2)
            float dL = gL - 1.0f;                  // [-1,1)
            bool  sL = dL >= 0.0f;
            unsigned cLx = sL ? b2.x : b0.x;
            unsigned cLy = sL ? b2.y : b0.y;
            unsigned cLz = sL ? b2.z : b0.z;
            unsigned cLw = sL ? b2.w : b0.w;

            float gH = fH + tg.w;                  // fH - sin + 1, [0,2)
            float dH = gH - 1.0f;
            bool  sH = dH >= 0.0f;
            unsigned cHx = sH ? h2.x : h0.x;
            unsigned cHy = sH ? h2.y : h0.y;
            unsigned cHz = sH ? h2.z : h0.z;
            unsigned cHw = sH ? h2.w : h0.w;

            __half2 f2L = __float2half2_rn(fL),  omfL = __hsub2(one2, f2L);
            __half2 f2H = __float2half2_rn(fH),  omfH = __hsub2(one2, f2H);
            __half2 wsL = __float2half2_rn(fabsf(dL));
            __half2 w1L = __hsub2(one2, wsL);
            __half2 wsH = __float2half2_rn(fabsf(dH));
            __half2 w1H = __hsub2(one2, wsH);

#define H2(v) (*reinterpret_cast<__half2*>(&(v)))
            // pixel0, L angle then H angle (merged accumulators)
            p0 = __hfma2(f2L, H2(b1.x), __hfma2(omfL, H2(b0.x), p0));
            p1 = __hfma2(f2L, H2(b1.y), __hfma2(omfL, H2(b0.y), p1));
            p2 = __hfma2(f2L, H2(b1.z), __hfma2(omfL, H2(b0.z), p2));
            p3 = __hfma2(f2L, H2(b1.w), __hfma2(omfL, H2(b0.w), p3));
            p0 = __hfma2(f2H, H2(h2.x), __hfma2(omfH, H2(h1.x), p0));
            p1 = __hfma2(f2H, H2(h2.y), __hfma2(omfH, H2(h1.y), p1));
            p2 = __hfma2(f2H, H2(h2.z), __hfma2(omfH, H2(h1.z), p2));
            p3 = __hfma2(f2H, H2(h2.w), __hfma2(omfH, H2(h1.w), p3));
            // pixel1, L angle: w1L*b1 + wsL*side
            q0 = __hfma2(w1L, H2(b1.x), __hfma2(wsL, H2(cLx), q0));
            q1 = __hfma2(w1L, H2(b1.y), __hfma2(wsL, H2(cLy), q1));
            q2 = __hfma2(w1L, H2(b1.z), __hfma2(wsL, H2(cLz), q2));
            q3 = __hfma2(w1L, H2(b1.w), __hfma2(wsL, H2(cLw), q3));
            // pixel1, H angle: w1H*h1 + wsH*side
            q0 = __hfma2(w1H, H2(h1.x), __hfma2(wsH, H2(cHx), q0));
            q1 = __hfma2(w1H, H2(h1.y), __hfma2(wsH, H2(cHy), q1));
            q2 = __hfma2(w1H, H2(h1.z), __hfma2(wsH, H2(cHz), q2));
            q3 = __hfma2(w1H, H2(h1.w), __hfma2(wsH, H2(cHw), q3));
#undef H2
        }

        float2 v;
        v = __half22float2(p0); fa[0]  += v.x; fa[1]  += v.y;
        v = __half22float2(p1); fa[2]  += v.x; fa[3]  += v.y;
        v = __half22float2(p2); fa[4]  += v.x; fa[5]  += v.y;
        v = __half22float2(p3); fa[6]  += v.x; fa[7]  += v.y;
        v = __half22float2(q0); fa[8]  += v.x; fa[9]  += v.y;
        v = __half22float2(q1); fa[10] += v.x; fa[11] += v.y;
        v = __half22float2(q2); fa[12] += v.x; fa[13] += v.y;
        v = __half22float2(q3); fa[14] += v.x; fa[15] += v.y;
    }

    int p0i = i0 * WIMG + j;
#pragma unroll
    for (int b = 0; b < NB; ++b) {
        out[b * (HIMG * WIMG) + p0i]        = fa[b]     * DTH;
        out[b * (HIMG * WIMG) + p0i + WIMG] = fa[8 + b] * DTH;
    }
}

// ---------------------------------------------------------------------------
extern "C" void kernel_launch(void* const* d_in, const int* in_sizes, int n_in,
                              void* d_out, int out_size) {
    const float* x = (const float*)d_in[0];   // [8,1,720,1024]
    const float* w = (const float*)d_in[1];   // [1,1,1,11]
    float* out = (float*)d_out;               // [8,1,512,512]

    conv_kernel<<<N_ANG, 256>>>(x, w);
    dim3 grid(WIMG / 8, HIMG / 32);           // (64, 16) = 1024 CTAs of 128
    bp_kernel<<<grid, 128>>>(out);
}

// round 17
// speedup vs baseline: 1.8419x; 1.0065x over previous
#include <cuda_runtime.h>
#include <cuda_fp16.h>

#define N_ANG 720
#define N_HALF 360
#define N_DET 1024
#define HIMG 512
#define WIMG 512
#define KSZ 11
#define NB 8

// Filtered sinogram, fp16, layout [angle][det_bin][batch0..7] -> 16B per bin.
__device__ __align__(16) __half g_h[N_ANG * N_DET * NB];

// ---- packed f32x2 helpers (SASS FFMA2/FADD2 — PTX-only on sm_103a) --------
typedef unsigned long long u64t;
__device__ __forceinline__ u64t pack2f(float lo, float hi) {
    u64t r; asm("mov.b64 %0, {%1, %2};" : "=l"(r) : "f"(lo), "f"(hi)); return r;
}
__device__ __forceinline__ float2 unpack2f(u64t v) {
    float2 r; asm("mov.b64 {%0, %1}, %2;" : "=f"(r.x), "=f"(r.y) : "l"(v)); return r;
}
__device__ __forceinline__ u64t fma2p(u64t a, u64t b, u64t c) {
    u64t d; asm("fma.rn.f32x2 %0, %1, %2, %3;" : "=l"(d) : "l"(a), "l"(b), "l"(c));
    return d;
}
__device__ __forceinline__ u64t add2p(u64t a, u64t b) {
    u64t d; asm("add.rn.f32x2 %0, %1, %2;" : "=l"(d) : "l"(a), "l"(b)); return d;
}
#define SIGNFLIP2 0x8000000080000000ULL
#define NEGMAGIC2 0xCB000000CB000000ULL   /* (-2^23, -2^23) */
#define NEGONE2   0xBF800000BF800000ULL   /* (-1, -1) */
#define C511P     0x43FFC00043FFC000ULL   /* (511.5, 511.5) */

// ---------------------------------------------------------------------------
// Stage 1: causal K=11 cross-correlation (unchanged).
// ---------------------------------------------------------------------------
__global__ void __launch_bounds__(256) conv_kernel(const float* __restrict__ x,
                                                   const float* __restrict__ w) {
    int tx = threadIdx.x;
    int a  = blockIdx.x;

    float wk[KSZ];
#pragma unroll
    for (int k = 0; k < KSZ; ++k) wk[k] = __ldg(w + k);

    uint4 out[4];
#pragma unroll
    for (int bp = 0; bp < 4; ++bp) {
        float acc[2][4];
#pragma unroll
        for (int s = 0; s < 2; ++s) {
            int b = bp * 2 + s;
            const float4* xb = reinterpret_cast<const float4*>(
                x + (size_t)b * (N_ANG * N_DET) + (size_t)a * N_DET);
            float win[16];
#pragma unroll
            for (int q = 0; q < 4; ++q) {
                int qi = tx - 3 + q;
                float4 v;
                if (qi >= 0) v = __ldg(xb + qi);
                else         v = make_float4(0.f, 0.f, 0.f, 0.f);
                win[q * 4 + 0] = v.x; win[q * 4 + 1] = v.y;
                win[q * 4 + 2] = v.z; win[q * 4 + 3] = v.w;
            }
#pragma unroll
            for (int di = 0; di < 4; ++di) {
                float acc_ = 0.f;
#pragma unroll
                for (int k = 0; k < KSZ; ++k)
                    acc_ = fmaf(wk[k], win[di + k + 2], acc_);
                acc[s][di] = acc_;
            }
        }
#pragma unroll
        for (int di = 0; di < 4; ++di) {
            __half2 h = __floats2half2_rn(acc[0][di], acc[1][di]);
            reinterpret_cast<unsigned int*>(&out[di])[bp] =
                *reinterpret_cast<unsigned int*>(&h);
        }
    }

    uint4* gp = reinterpret_cast<uint4*>(g_h) + ((size_t)a << 10) + (tx << 2);
#pragma unroll
    for (int di = 0; di < 4; ++di) gp[di] = out[di];
}

// ---------------------------------------------------------------------------
// Stage 2: backprojection. One thread = pixel pair (i, i+1) at one j, all 8
// batches, complementary angle pairs (a, a+360); 3 LDG.128/angle serve both
// pixels; pixel1 taps via the |g-1| identity (4 SELs/angle). Address/weight
// fp32 math packed as f32x2 (uL,uH lanes) -> FFMA2/FADD2; fp32 flush
// accumulators packed too (8 FADD2 instead of 16 FADD per flush).
// launch_bounds(128,7): grid places <=7 CTAs/SM anyway -> free reg headroom.
// ---------------------------------------------------------------------------
__global__ void __launch_bounds__(128, 7) bp_kernel(float* __restrict__ out) {
    __shared__ float4 trigA[N_HALF];  // (c*IDS, c*IDS, s*IDS, s*IDS) broadcast-packed
    __shared__ float2 trigB[N_HALF];  // (cos, 1-sin)

    const float DTH = 3.14159265358979323846f / (float)N_ANG;
    const float DX  = 2.0f / (float)HIMG;
    const float INV_DS = (float)N_DET / 4.0f;   // 256

    int tx = threadIdx.x;
    for (int a = tx; a < N_HALF; a += blockDim.x) {
        float th = ((float)a + 0.5f) * DTH;
        float s, c;
        sincosf(th, &s, &c);
        trigA[a] = make_float4(c * INV_DS, c * INV_DS, s * INV_DS, s * INV_DS);
        trigB[a] = make_float2(c, 1.0f - s);
    }
    __syncthreads();

    int j  = (blockIdx.x << 3) + (tx & 7);
    int ip = (blockIdx.y << 4) + (tx >> 3);     // i-pair index (16 per CTA)
    int i0 = ip << 1;
    float xc = fmaf((float)i0 + 0.5f, DX, -1.0f);
    float yc = fmaf((float)j  + 0.5f, DX, -1.0f);

    const u64t XX = pack2f(xc, yc);     // lane0 mults for uL, uH
    const u64t YX = pack2f(yc, -xc);    // lane1 mults

    u64t fa2[16 / 2];                   // 8 packed float2: [pix0 b01..b67, pix1 ...]
    u64t fq2[16 / 2 - 4 + 4];           // (unused pad avoided below)
    (void)fq2;
    u64t faP[4], faQ[4];
#pragma unroll
    for (int b = 0; b < 4; ++b) { faP[b] = 0ULL; faQ[b] = 0ULL; }
    (void)fa2;

    const char* gbase = reinterpret_cast<const char*>(g_h);
    const __half2 one2  = __float2half2_rn(1.0f);
    const __half2 zero2 = __float2half2_rn(0.0f);

#pragma unroll 1
    for (int a0 = 0; a0 < N_HALF; a0 += 4) {
        __half2 p0 = zero2, p1 = zero2, p2 = zero2, p3 = zero2;   // pixel0
        __half2 q0 = zero2, q1 = zero2, q2 = zero2, q3 = zero2;   // pixel1

#pragma unroll
        for (int k = 0; k < 4; ++k) {
            int a = a0 + k;
            float4 tA = trigA[a];
            float2 tB = trigB[a];
            u64t bx = *reinterpret_cast<const u64t*>(&tA.x);   // (cI, cI)
            u64t by = *reinterpret_cast<const u64t*>(&tA.z);   // (sI, sI)
            u64t zw = *reinterpret_cast<const u64t*>(&tB);     // (cos, 1-sin)

            // ---- packed addresses: (uL, uH) in one chain ----
            u64t u2p = fma2p(XX, bx, fma2p(YX, by, C511P));
            float2 uu = unpack2f(u2p);
            float tL = __fadd_rd(uu.x, 8388608.0f);            // scalar rd magic
            float tH = __fadd_rd(uu.y, 8388608.0f);
            u64t t2p  = pack2f(tL, tH);
            u64t fi2p = add2p(t2p, NEGMAGIC2);                 // (fiL, fiH) exact
            u64t f2p  = add2p(u2p, fi2p ^ SIGNFLIP2);          // (fL, fH) exact
            float2 ff = unpack2f(f2p);
            unsigned offL = (__float_as_uint(tL) << 9) >> 5;   // base*16
            unsigned offH = (__float_as_uint(tH) << 9) >> 5;

            // ---- 6 LDG.128 ----
            const uint4* pl = reinterpret_cast<const uint4*>(
                gbase + ((size_t)a << 14) + offL);
            const uint4* ph = reinterpret_cast<const uint4*>(
                gbase + ((size_t)(a + N_HALF) << 14) + offH) - 1;   // base-1
            uint4 b0 = __ldg(pl);       // L: base
            uint4 b1 = __ldg(pl + 1);   // L: base+1
            uint4 b2 = __ldg(pl + 2);   // L: base+2
            uint4 h0 = __ldg(ph);       // H: base-1
            uint4 h1 = __ldg(ph + 1);   // H: base
            uint4 h2 = __ldg(ph + 2);   // H: base+1

            // ---- packed pixel1 offsets: (gL,gH), (dL,dH) ----
            u64t g2p = add2p(f2p, zw);                          // (fL+c, fH+1-s)
            u64t d2p = add2p(g2p, NEGONE2);
            float2 dd = unpack2f(d2p);
            bool  sL = dd.x >= 0.0f;
            bool  sH = dd.y >= 0.0f;
            unsigned cLx = sL ? b2.x : b0.x;
            unsigned cLy = sL ? b2.y : b0.y;
            unsigned cLz = sL ? b2.z : b0.z;
            unsigned cLw = sL ? b2.w : b0.w;
            unsigned cHx = sH ? h2.x : h0.x;
            unsigned cHy = sH ? h2.y : h0.y;
            unsigned cHz = sH ? h2.z : h0.z;
            unsigned cHw = sH ? h2.w : h0.w;

            __half2 f2L = __float2half2_rn(ff.x), omfL = __hsub2(one2, f2L);
            __half2 f2H = __float2half2_rn(ff.y), omfH = __hsub2(one2, f2H);
            __half2 wsL = __float2half2_rn(fabsf(dd.x));
            __half2 w1L = __hsub2(one2, wsL);
            __half2 wsH = __float2half2_rn(fabsf(dd.y));
            __half2 w1H = __hsub2(one2, wsH);

#define H2(v) (*reinterpret_cast<__half2*>(&(v)))
            // pixel0, L angle then H angle (merged accumulators)
            p0 = __hfma2(f2L, H2(b1.x), __hfma2(omfL, H2(b0.x), p0));
            p1 = __hfma2(f2L, H2(b1.y), __hfma2(omfL, H2(b0.y), p1));
            p2 = __hfma2(f2L, H2(b1.z), __hfma2(omfL, H2(b0.z), p2));
            p3 = __hfma2(f2L, H2(b1.w), __hfma2(omfL, H2(b0.w), p3));
            p0 = __hfma2(f2H, H2(h2.x), __hfma2(omfH, H2(h1.x), p0));
            p1 = __hfma2(f2H, H2(h2.y), __hfma2(omfH, H2(h1.y), p1));
            p2 = __hfma2(f2H, H2(h2.z), __hfma2(omfH, H2(h1.z), p2));
            p3 = __hfma2(f2H, H2(h2.w), __hfma2(omfH, H2(h1.w), p3));
            // pixel1, L angle: w1L*b1 + wsL*side
            q0 = __hfma2(w1L, H2(b1.x), __hfma2(wsL, H2(cLx), q0));
            q1 = __hfma2(w1L, H2(b1.y), __hfma2(wsL, H2(cLy), q1));
            q2 = __hfma2(w1L, H2(b1.z), __hfma2(wsL, H2(cLz), q2));
            q3 = __hfma2(w1L, H2(b1.w), __hfma2(wsL, H2(cLw), q3));
            // pixel1, H angle: w1H*h1 + wsH*side
            q0 = __hfma2(w1H, H2(h1.x), __hfma2(wsH, H2(cHx), q0));
            q1 = __hfma2(w1H, H2(h1.y), __hfma2(wsH, H2(cHy), q1));
            q2 = __hfma2(w1H, H2(h1.z), __hfma2(wsH, H2(cHz), q2));
            q3 = __hfma2(w1H, H2(h1.w), __hfma2(wsH, H2(cHw), q3));
#undef H2
        }

        // ---- packed fp32 flush (8 FADD2 instead of 16 FADD) ----
        float2 v;
        v = __half22float2(p0); faP[0] = add2p(faP[0], pack2f(v.x, v.y));
        v = __half22float2(p1); faP[1] = add2p(faP[1], pack2f(v.x, v.y));
        v = __half22float2(p2); faP[2] = add2p(faP[2], pack2f(v.x, v.y));
        v = __half22float2(p3); faP[3] = add2p(faP[3], pack2f(v.x, v.y));
        v = __half22float2(q0); faQ[0] = add2p(faQ[0], pack2f(v.x, v.y));
        v = __half22float2(q1); faQ[1] = add2p(faQ[1], pack2f(v.x, v.y));
        v = __half22float2(q2); faQ[2] = add2p(faQ[2], pack2f(v.x, v.y));
        v = __half22float2(q3); faQ[3] = add2p(faQ[3], pack2f(v.x, v.y));
    }

    int p0i = i0 * WIMG + j;
#pragma unroll
    for (int b = 0; b < 4; ++b) {
        float2 vp = unpack2f(faP[b]);
        float2 vq = unpack2f(faQ[b]);
        out[(2 * b)     * (HIMG * WIMG) + p0i]        = vp.x * DTH;
        out[(2 * b + 1) * (HIMG * WIMG) + p0i]        = vp.y * DTH;
        out[(2 * b)     * (HIMG * WIMG) + p0i + WIMG] = vq.x * DTH;
        out[(2 * b + 1) * (HIMG * WIMG) + p0i + WIMG] = vq.y * DTH;
    }
}

// ---------------------------------------------------------------------------
extern "C" void kernel_launch(void* const* d_in, const int* in_sizes, int n_in,
                              void* d_out, int out_size) {
    const float* x = (const float*)d_in[0];   // [8,1,720,1024]
    const float* w = (const float*)d_in[1];   // [1,1,1,11]
    float* out = (float*)d_out;               // [8,1,512,512]

    conv_kernel<<<N_ANG, 256>>>(x, w);
    dim3 grid(WIMG / 8, HIMG / 32);           // (64, 16) = 1024 CTAs of 128
    bp_kernel<<<grid, 128>>>(out);
}